// round 17
// baseline (speedup 1.0000x reference)
#include <cuda_runtime.h>

#define NI 16384          // inputs per batch row
#define ND 65536          // detectors
#define KK 32             // members per detector (== warp size)
#define BB 32             // batch
#define NCHUNK 32         // detector tiles
#define DET_PER_CTA (ND / NCHUNK)   // 2048
#define THREADS 1024
#define WARPS (THREADS / 32)        // 32
#define DET_PER_WARP (DET_PER_CTA / WARPS)  // 64
#define SMEM_BYTES (NI * 8)         // 128KB: uint2 = 4 x key16 per input
#define NQUAD (BB / 4)              // 8 batch quads

// Global scratch (allocation-free rule; zero-initialized at module load).
// spike(b,i) <=> wins(b,i) == memberships(i): each detector contributes one
// winner slot + K-1 loser slots, so stat = M - W. Duplicate ids and exact
// value ties preserved (winner = lowest max slot), matching jnp.argmax.
// rel_err 0.0 across R6-R16 with this identity.
// Invariant at kernel_launch entry: g_M == 0 and g_W == 0 (finalize resets
// both; statics start zeroed), so the launch is replay-deterministic.
__device__ unsigned g_M[NI];
__device__ unsigned g_W[BB * NI];

// Order-preserving float -> unsigned key: x >= y (as floats) iff
// key(x) >= key(y) as unsigned. Equal floats -> equal keys.
__device__ __forceinline__ unsigned f32_order_key(unsigned u) {
    return u ^ (((int)u >> 31) | 0x80000000u);
}

// Winner resolution for one batch: key16 is a monotone truncation, so a
// UNIQUE warp-max key16 identifies the exact fp32 winner. On ties
// (warp-uniform, rare) the candidate lanes reload the exact fp32 value
// from the L2-hot x row and re-reduce — bit-exact argmax, lowest-slot
// tie-break. The winning lane fires one gmem RED.ADD.
__device__ __forceinline__ void resolve_winner(
    unsigned k16, int id, const float* __restrict__ xrow,
    unsigned* __restrict__ Wrow, int lane)
{
    unsigned m = __reduce_max_sync(0xffffffffu, k16);
    unsigned bal = __ballot_sync(0xffffffffu, k16 == m);
    if (__popc(bal) > 1) {                       // warp-uniform, ~3-5%
        bool cand = (bal >> lane) & 1u;
        unsigned ek = 0u;
        if (cand) ek = f32_order_key(__float_as_uint(__ldg(xrow + id)));
        unsigned em = __reduce_max_sync(0xffffffffu, ek);
        bal = __ballot_sync(0xffffffffu, cand && ek == em);
    }
    if (lane == __ffs(bal) - 1)
        atomicAdd(Wrow + id, 1u);                // REDG, fire-and-forget
}

// One CTA = one detector tile x one batch QUAD. One LDS.64 gather returns
// 4 batches' 16-bit keys; the det LDG and loop overhead are amortized 4x.
// Depth-2 pipeline: det ids prefetched TWO iterations ahead (LDG), gathers
// ONE ahead (LDS on ids loaded a full iteration earlier).
// Membership histogram inline: rows counted when (i & 7) == quad ->
// exactly once per det row across the 8 quad-groups.
__global__ void __launch_bounds__(THREADS, 1) winner_kernel(
    const float* __restrict__ x,
    const int*   __restrict__ det)
{
    extern __shared__ uint2 xs2[];               // 128KB: 4 x key16

    const int tid   = threadIdx.x;
    const int chunk = blockIdx.x;               // 0..NCHUNK-1
    const int quad  = blockIdx.y;               // 0..NQUAD-1
    const int b0    = quad * 4;

    // Prologue: pack 4 batches' truncated keys per input (coalesced loads).
    const float* row0 = x + (size_t)b0 * NI;
    #pragma unroll
    for (int i = tid; i < NI; i += THREADS) {
        unsigned k0 = f32_order_key(__float_as_uint(__ldg(row0 + i)));
        unsigned k1 = f32_order_key(__float_as_uint(__ldg(row0 + NI + i)));
        unsigned k2 = f32_order_key(__float_as_uint(__ldg(row0 + 2 * NI + i)));
        unsigned k3 = f32_order_key(__float_as_uint(__ldg(row0 + 3 * NI + i)));
        xs2[i] = make_uint2((k0 & 0xFFFF0000u) | (k1 >> 16),
                            (k2 & 0xFFFF0000u) | (k3 >> 16));
    }
    __syncthreads();

    const int lane = tid & 31;
    const int warp = tid >> 5;
    unsigned* W0 = g_W + (size_t)b0 * NI;

    // Warp w owns DET_PER_WARP consecutive detector rows; one row == 128B
    // == one coalesced warp load.
    const int* dbase = det
        + ((size_t)(chunk * DET_PER_CTA + warp * DET_PER_WARP)) * KK + lane;

    // Pipeline prime: ids for iters 0 and 1, gather for iter 0.
    int   id_c = __ldg(dbase);
    int   id_n = __ldg(dbase + KK);
    uint2 p_c  = xs2[id_c];

    #pragma unroll 4
    for (int i = 0; i < DET_PER_WARP; i++) {
        // LDG two ahead; LDS one ahead (id loaded a full iteration ago).
        int id_f = 0;
        if (i + 2 < DET_PER_WARP) id_f = __ldg(dbase + (i + 2) * KK);
        uint2 p_n = make_uint2(0u, 0u);
        if (i + 1 < DET_PER_WARP) p_n = xs2[id_n];

        // Inline membership histogram (exactly-once across quad groups).
        if ((i & (NQUAD - 1)) == quad)
            atomicAdd(&g_M[id_c], 1u);           // spread REDG

        resolve_winner(p_c.x >> 16,     id_c, row0,          W0,          lane);
        resolve_winner(p_c.x & 0xFFFFu, id_c, row0 + NI,     W0 + NI,     lane);
        resolve_winner(p_c.y >> 16,     id_c, row0 + 2 * NI, W0 + 2 * NI, lane);
        resolve_winner(p_c.y & 0xFFFFu, id_c, row0 + 3 * NI, W0 + 3 * NI, lane);

        id_c = id_n; id_n = id_f; p_c = p_n;
    }
}

// Finalize (R13, measured ~5.5us): 1024 blocks x 512 threads; block j owns
// 16 columns for ALL 32 batches (one element per thread; consecutive tids
// -> consecutive columns, coalesced). g_M[col] is read only inside its
// owning block, so after __syncthreads() the block resets it. g_W reset
// inline (own address).
__global__ void __launch_bounds__(512) finalize_kernel(float* __restrict__ out) {
    const int col = blockIdx.x * 16 + (threadIdx.x & 15);
    const int b   = threadIdx.x >> 4;            // 0..31
    const int idx = b * NI + col;
    out[idx] = (g_W[idx] == g_M[col]) ? 1.0f : 0.0f;
    g_W[idx] = 0u;
    __syncthreads();
    if (threadIdx.x < 16)
        g_M[blockIdx.x * 16 + threadIdx.x] = 0u;
}

extern "C" void kernel_launch(void* const* d_in, const int* in_sizes, int n_in,
                              void* d_out, int out_size) {
    const float* x   = (const float*)d_in[0];   // [32, 16384] f32
    const int*   det = (const int*)d_in[1];     // [65536, 32] i32
    float*       out = (float*)d_out;           // [32, 16384] f32

    (void)in_sizes; (void)n_in; (void)out_size;

    cudaFuncSetAttribute(winner_kernel,
                         cudaFuncAttributeMaxDynamicSharedMemorySize,
                         SMEM_BYTES);

    // 1) Winner counting + inline membership histogram (needs M=W=0,
    //    guaranteed by the previous finalize / static zero-init).
    dim3 grid(NCHUNK, NQUAD);
    winner_kernel<<<grid, THREADS, SMEM_BYTES>>>(x, det);
    // 2) spike = (wins == memberships); resets W and M for the next call.
    finalize_kernel<<<NI / 16, 512>>>(out);
}